// round 1
// baseline (speedup 1.0000x reference)
#include <cuda_runtime.h>

// Problem constants
#define B_ 16
#define S_ 2048
#define H_ 512
#define W_ 4
#define L_ 2
#define SP_ (S_ + 2 * W_)   // 2056 padded rows per batch

// Scratch in device globals (allocation-free rule)
__device__ float g_padded[B_ * SP_ * H_];   // [B, S+2W, H]
__device__ float g_lo[B_ * S_ * H_];        // left activations  [B*S, H]
__device__ float g_ro[B_ * S_ * H_];        // right activations [B*S, H]
__device__ float g_h[B_ * S_ * H_];         // hidden scratch    [B*S, H]
__device__ float g_stats[B_ * S_ * 2];      // per-row (mean, rstd)

// ---------------------------------------------------------------------------
// Build padded [B, S+2W, H] = [left_padding ; inputs ; right_padding]
// ---------------------------------------------------------------------------
__global__ void pad_kernel(const float* __restrict__ inp,
                           const float* __restrict__ lp,
                           const float* __restrict__ rp) {
    const int H4 = H_ / 4;
    int idx = blockIdx.x * blockDim.x + threadIdx.x;
    int total = B_ * SP_ * H4;
    if (idx >= total) return;
    int h4 = idx % H4;
    int t = idx / H4;
    int p = t % SP_;
    int b = t / SP_;
    float4 v;
    if (p < W_) {
        v = ((const float4*)lp)[p * H4 + h4];
    } else if (p < W_ + S_) {
        v = ((const float4*)inp)[((size_t)b * S_ + (p - W_)) * H4 + h4];
    } else {
        v = ((const float4*)rp)[(p - W_ - S_) * H4 + h4];
    }
    ((float4*)g_padded)[idx] = v;
}

// ---------------------------------------------------------------------------
// Per-row LayerNorm statistics: one warp per row of [B*S, H]
// ---------------------------------------------------------------------------
__global__ void stats_kernel(int side) {
    const float* X = side ? g_ro : g_lo;
    int gwarp = (blockIdx.x * blockDim.x + threadIdx.x) >> 5;
    int lane = threadIdx.x & 31;
    if (gwarp >= B_ * S_) return;
    const float4* x = (const float4*)(X + (size_t)gwarp * H_);
    float s = 0.f, sq = 0.f;
#pragma unroll
    for (int j = 0; j < 4; j++) {
        float4 v = x[lane + 32 * j];
        s  += v.x + v.y + v.z + v.w;
        sq += v.x * v.x + v.y * v.y + v.z * v.z + v.w * v.w;
    }
#pragma unroll
    for (int o = 16; o; o >>= 1) {
        s  += __shfl_xor_sync(0xffffffffu, s, o);
        sq += __shfl_xor_sync(0xffffffffu, sq, o);
    }
    if (lane == 0) {
        float mean = s * (1.0f / H_);
        float var = sq * (1.0f / H_) - mean * mean;
        g_stats[2 * gwarp] = mean;
        g_stats[2 * gwarp + 1] = rsqrtf(fmaxf(var, 0.f) + 1e-5f);
    }
}

// ---------------------------------------------------------------------------
// Tiled fp32 GEMM, 128(M) x 64(N) tile, BK=16, 256 threads, 8x4 per thread.
//
// MODE 0: wide projection. A rows are overlapping windows in g_padded
//         (row stride H, row length K=W*H). C = relu(A@W + bias) -> g_lo/g_ro.
// MODE 1: LN-fused. A = LN(x) applied on load via g_stats/gamma/beta.
//         C = relu(A@W + bias) -> g_h.
// MODE 2: out. A = g_h. y = x + A@W + bias. Writes y to x (in place),
//         to all_layers region, and optionally last_layers region.
// ---------------------------------------------------------------------------
template <int MODE>
__global__ __launch_bounds__(256)
void gemm_kernel(int side, int K,
                 const float* __restrict__ Wm,    // [K, H]
                 const float* __restrict__ bias,  // [H]
                 const float* __restrict__ gamma, // MODE 1
                 const float* __restrict__ lnb,   // MODE 1
                 float* __restrict__ out_all,     // MODE 2 (pre-offset to layer/side)
                 float* __restrict__ out_last) {  // MODE 2 (may be null)
    constexpr int BM = 128, BN = 64, BK = 16;
    __shared__ float As[BK][BM];
    __shared__ float Bs[BK][BN];

    const int tid = threadIdx.x;
    const int tx = tid & 15;    // N direction (4 cols each)
    const int ty = tid >> 4;    // M direction (8 rows each)
    const int n0 = blockIdx.x * BN;

    float* Xres = side ? g_ro : g_lo;

    size_t m0;
    const float* Abase;
    float* Cdst;
    if (MODE == 0) {
        int s0 = blockIdx.y * BM;
        m0 = (size_t)blockIdx.z * S_ + s0;
        Abase = g_padded + ((size_t)blockIdx.z * SP_ + s0) * H_ + (side ? (W_ + 1) * H_ : 0);
        Cdst = Xres;
    } else if (MODE == 1) {
        m0 = (size_t)blockIdx.y * BM;
        Abase = Xres + m0 * H_;
        Cdst = g_h;
    } else {
        m0 = (size_t)blockIdx.y * BM;
        Abase = g_h + m0 * H_;
        Cdst = Xres;
    }

    const int arow = tid >> 1;        // 0..127
    const int ak = (tid & 1) * 8;     // 0 or 8
    const int bkr = tid >> 4;         // 0..15
    const int bnc = (tid & 15) * 4;   // 0..60

    float mean = 0.f, rstd = 0.f;
    if (MODE == 1) {
        mean = g_stats[2 * (m0 + arow)];
        rstd = g_stats[2 * (m0 + arow) + 1];
    }

    float acc[8][4];
#pragma unroll
    for (int i = 0; i < 8; i++)
#pragma unroll
        for (int j = 0; j < 4; j++) acc[i][j] = 0.f;

    const float* aptr = Abase + (size_t)arow * H_ + ak;

    for (int k0 = 0; k0 < K; k0 += BK) {
        float4 a0 = *(const float4*)(aptr + k0);
        float4 a1 = *(const float4*)(aptr + k0 + 4);
        if (MODE == 1) {
            float4 g0 = *(const float4*)(gamma + k0 + ak);
            float4 g1 = *(const float4*)(gamma + k0 + ak + 4);
            float4 q0 = *(const float4*)(lnb + k0 + ak);
            float4 q1 = *(const float4*)(lnb + k0 + ak + 4);
            a0.x = (a0.x - mean) * rstd * g0.x + q0.x;
            a0.y = (a0.y - mean) * rstd * g0.y + q0.y;
            a0.z = (a0.z - mean) * rstd * g0.z + q0.z;
            a0.w = (a0.w - mean) * rstd * g0.w + q0.w;
            a1.x = (a1.x - mean) * rstd * g1.x + q1.x;
            a1.y = (a1.y - mean) * rstd * g1.y + q1.y;
            a1.z = (a1.z - mean) * rstd * g1.z + q1.z;
            a1.w = (a1.w - mean) * rstd * g1.w + q1.w;
        }
        As[ak + 0][arow] = a0.x;
        As[ak + 1][arow] = a0.y;
        As[ak + 2][arow] = a0.z;
        As[ak + 3][arow] = a0.w;
        As[ak + 4][arow] = a1.x;
        As[ak + 5][arow] = a1.y;
        As[ak + 6][arow] = a1.z;
        As[ak + 7][arow] = a1.w;
        *(float4*)&Bs[bkr][bnc] = *(const float4*)(Wm + (size_t)(k0 + bkr) * H_ + n0 + bnc);
        __syncthreads();
#pragma unroll
        for (int kk = 0; kk < BK; kk++) {
            float4 av0 = *(const float4*)&As[kk][ty * 8];
            float4 av1 = *(const float4*)&As[kk][ty * 8 + 4];
            float4 bv = *(const float4*)&Bs[kk][tx * 4];
            float a_[8] = {av0.x, av0.y, av0.z, av0.w, av1.x, av1.y, av1.z, av1.w};
            float b_[4] = {bv.x, bv.y, bv.z, bv.w};
#pragma unroll
            for (int i = 0; i < 8; i++)
#pragma unroll
                for (int j = 0; j < 4; j++)
                    acc[i][j] = fmaf(a_[i], b_[j], acc[i][j]);
        }
        __syncthreads();
    }

    const float4 bb = *(const float4*)(bias + n0 + tx * 4);
    const int ccol = n0 + tx * 4;
#pragma unroll
    for (int i = 0; i < 8; i++) {
        size_t m = m0 + ty * 8 + i;
        float4 v;
        v.x = acc[i][0] + bb.x;
        v.y = acc[i][1] + bb.y;
        v.z = acc[i][2] + bb.z;
        v.w = acc[i][3] + bb.w;
        if (MODE != 2) {
            v.x = fmaxf(v.x, 0.f);
            v.y = fmaxf(v.y, 0.f);
            v.z = fmaxf(v.z, 0.f);
            v.w = fmaxf(v.w, 0.f);
            *(float4*)&Cdst[m * H_ + ccol] = v;
        } else {
            float4 r = *(const float4*)&Xres[m * H_ + ccol];
            v.x += r.x; v.y += r.y; v.z += r.z; v.w += r.w;
            *(float4*)&Cdst[m * H_ + ccol] = v;
            size_t bidx = m / S_, sidx = m % S_;
            // all_layers [L, S, B, 2H]: out_all already offset to (layer, side)
            *(float4*)&out_all[(sidx * B_ + bidx) * (size_t)(2 * H_) + ccol] = v;
            if (out_last)
                *(float4*)&out_last[(bidx * S_ + sidx) * (size_t)(2 * H_) + ccol] = v;
        }
    }
}

extern "C" void kernel_launch(void* const* d_in, const int* in_sizes, int n_in,
                              void* d_out, int out_size) {
    const float* inputs = (const float*)d_in[0];
    const float* lp     = (const float*)d_in[1];
    const float* rp     = (const float*)d_in[2];
    const float* Wl     = (const float*)d_in[3];
    const float* bl     = (const float*)d_in[4];
    const float* Wr     = (const float*)d_in[5];
    const float* br     = (const float*)d_in[6];
    const float* lw1    = (const float*)d_in[7];
    const float* lb1    = (const float*)d_in[8];
    const float* lw2    = (const float*)d_in[9];
    const float* lb2    = (const float*)d_in[10];
    const float* lg     = (const float*)d_in[11];
    const float* lbeta  = (const float*)d_in[12];
    const float* rw1    = (const float*)d_in[13];
    const float* rb1    = (const float*)d_in[14];
    const float* rw2    = (const float*)d_in[15];
    const float* rb2    = (const float*)d_in[16];
    const float* rg     = (const float*)d_in[17];
    const float* rbeta  = (const float*)d_in[18];
    float* out = (float*)d_out;

    (void)in_sizes; (void)n_in; (void)out_size;

    // 1) materialize padded sequence
    int padTotal = B_ * SP_ * (H_ / 4);
    pad_kernel<<<(padTotal + 255) / 256, 256>>>(inputs, lp, rp);

    // 2) wide projections: lo = relu(left @ Wl + bl), ro = relu(right @ Wr + br)
    dim3 gwide(H_ / 64, S_ / 128, B_);
    gemm_kernel<0><<<gwide, 256>>>(0, W_ * H_, Wl, bl, nullptr, nullptr, nullptr, nullptr);
    gemm_kernel<0><<<gwide, 256>>>(1, W_ * H_, Wr, br, nullptr, nullptr, nullptr, nullptr);

    // 3) residual FF layers
    dim3 glayer(H_ / 64, (B_ * S_) / 128, 1);
    int statsBlocks = (B_ * S_) / 8;  // 8 warps per block, 1 row per warp
    for (int i = 0; i < L_; i++) {
        for (int side = 0; side < 2; side++) {
            const float* w1 = (side ? rw1 : lw1) + (size_t)i * H_ * H_;
            const float* b1 = (side ? rb1 : lb1) + (size_t)i * H_;
            const float* w2 = (side ? rw2 : lw2) + (size_t)i * H_ * H_;
            const float* b2 = (side ? rb2 : lb2) + (size_t)i * H_;
            const float* gg = (side ? rg : lg) + (size_t)i * H_;
            const float* bt = (side ? rbeta : lbeta) + (size_t)i * H_;

            stats_kernel<<<statsBlocks, 256>>>(side);
            gemm_kernel<1><<<glayer, 256>>>(side, H_, w1, b1, gg, bt, nullptr, nullptr);

            float* oall = out + (size_t)i * S_ * B_ * 2 * H_ + (size_t)side * H_;
            float* olast = (i == L_ - 1)
                ? out + (size_t)L_ * S_ * B_ * 2 * H_ + (size_t)side * H_
                : nullptr;
            gemm_kernel<2><<<glayer, 256>>>(side, H_, w2, b2, nullptr, nullptr, oall, olast);
        }
    }
}

// round 3
// speedup vs baseline: 3.1479x; 3.1479x over previous
#include <cuda_runtime.h>
#include <cstdint>

#define B_ 16
#define S_ 2048
#define H_ 512
#define W_ 4
#define L_ 2
#define SP_ (S_ + 2 * W_)   // 2056
#define BS_ (B_ * S_)       // 32768

// ---------------------------------------------------------------------------
// Scratch (allocation-free rule: __device__ globals, referenced in-kernel)
// ---------------------------------------------------------------------------
__device__ __align__(256) float g_padded[B_ * SP_ * H_];
__device__ __align__(256) float g_lo[BS_ * H_];
__device__ __align__(256) float g_ro[BS_ * H_];
__device__ __align__(256) float g_h[BS_ * H_];
__device__ __align__(256) float g_ln[BS_ * H_];

// ---------------------------------------------------------------------------
// PTX helpers
// ---------------------------------------------------------------------------
__device__ __forceinline__ uint32_t smem_u32(const void* p) {
    uint32_t a;
    asm("{ .reg .u64 t; cvta.to.shared.u64 t, %1; cvt.u32.u64 %0, t; }" : "=r"(a) : "l"(p));
    return a;
}
__device__ __forceinline__ void cp_async16(uint32_t dst, const void* src) {
    asm volatile("cp.async.cg.shared.global [%0], [%1], 16;" :: "r"(dst), "l"(src) : "memory");
}
template <int N>
__device__ __forceinline__ void cp_wait() {
    asm volatile("cp.async.wait_group %0;" :: "n"(N) : "memory");
}
#define CP_COMMIT() asm volatile("cp.async.commit_group;" ::: "memory")

__device__ __forceinline__ uint32_t f2tf32(float x) {
    uint32_t r;
    asm("cvt.rna.tf32.f32 %0, %1;" : "=r"(r) : "f"(x));
    return r;
}
__device__ __forceinline__ void mma_tf32(float c[4], const uint32_t a[4], const uint32_t b[2]) {
    asm volatile(
        "mma.sync.aligned.m16n8k8.row.col.f32.tf32.tf32.f32 "
        "{%0,%1,%2,%3}, {%4,%5,%6,%7}, {%8,%9}, {%0,%1,%2,%3};"
        : "+f"(c[0]), "+f"(c[1]), "+f"(c[2]), "+f"(c[3])
        : "r"(a[0]), "r"(a[1]), "r"(a[2]), "r"(a[3]), "r"(b[0]), "r"(b[1]));
}

// ---------------------------------------------------------------------------
// pad: [left ; inputs ; right] -> g_padded
// ---------------------------------------------------------------------------
__global__ void pad_kernel(const float* __restrict__ inp,
                           const float* __restrict__ lp,
                           const float* __restrict__ rp) {
    const int H4 = H_ / 4;
    int idx = blockIdx.x * blockDim.x + threadIdx.x;
    if (idx >= B_ * SP_ * H4) return;
    int h4 = idx % H4;
    int t = idx / H4;
    int p = t % SP_;
    int b = t / SP_;
    float4 v;
    if (p < W_) v = ((const float4*)lp)[p * H4 + h4];
    else if (p < W_ + S_) v = ((const float4*)inp)[((size_t)b * S_ + (p - W_)) * H4 + h4];
    else v = ((const float4*)rp)[(p - W_ - S_) * H4 + h4];
    ((float4*)g_padded)[idx] = v;
}

// ---------------------------------------------------------------------------
// LayerNorm, one warp per row: g_ln = gamma*(X-mean)*rstd + beta
// ---------------------------------------------------------------------------
__global__ void ln_kernel(int side, const float* __restrict__ gam,
                          const float* __restrict__ bet) {
    const float* X = side ? g_ro : g_lo;
    int gw = (blockIdx.x * blockDim.x + threadIdx.x) >> 5;
    int l = threadIdx.x & 31;
    const float4* x = (const float4*)(X + (size_t)gw * H_);
    float4 v[4];
    float s = 0.f, sq = 0.f;
#pragma unroll
    for (int j = 0; j < 4; j++) {
        v[j] = x[l + 32 * j];
        s += v[j].x + v[j].y + v[j].z + v[j].w;
        sq += v[j].x * v[j].x + v[j].y * v[j].y + v[j].z * v[j].z + v[j].w * v[j].w;
    }
#pragma unroll
    for (int o = 16; o; o >>= 1) {
        s += __shfl_xor_sync(0xffffffffu, s, o);
        sq += __shfl_xor_sync(0xffffffffu, sq, o);
    }
    float mean = s * (1.0f / H_);
    float var = sq * (1.0f / H_) - mean * mean;
    float rstd = rsqrtf(fmaxf(var, 0.f) + 1e-5f);
    float4* y = (float4*)(g_ln + (size_t)gw * H_);
    const float4* g4 = (const float4*)gam;
    const float4* b4 = (const float4*)bet;
#pragma unroll
    for (int j = 0; j < 4; j++) {
        float4 gv = g4[l + 32 * j], bv = b4[l + 32 * j], o;
        o.x = (v[j].x - mean) * rstd * gv.x + bv.x;
        o.y = (v[j].y - mean) * rstd * gv.y + bv.y;
        o.z = (v[j].z - mean) * rstd * gv.z + bv.z;
        o.w = (v[j].w - mean) * rstd * gv.w + bv.w;
        y[l + 32 * j] = o;
    }
}

// ---------------------------------------------------------------------------
// tf32 mma.sync GEMM: 128x128 tile, BK=32, 3-stage cp.async pipeline.
// 256 threads = 8 warps (2 x 4), warp tile 64x32, mma m16n8k8.
// MODE 0: A = windows of g_padded,      C = relu(A@W + b)        -> g_lo/g_ro
// MODE 1: A = g_ln,                     C = relu(A@W + b)        -> g_h
// MODE 2: A = g_h, y = X + A@W + b -> X (in place), out_all, out_last
// ---------------------------------------------------------------------------
constexpr int AS_STRIDE = 36;                       // floats per A smem row
constexpr int BS_STRIDE = 136;                      // floats per B smem row
constexpr int A_STAGE_F = 128 * AS_STRIDE;          // 4608 floats
constexpr int B_STAGE_F = 32 * BS_STRIDE;           // 4352 floats
constexpr int STAGE_F = A_STAGE_F + B_STAGE_F;      // 8960 floats = 35840 B
constexpr int SMEM_BYTES = 3 * STAGE_F * 4;         // 107520 B

template <int MODE, int KT>  // KT = K / 32
__global__ void __launch_bounds__(256, 1)
tc_gemm(int side, const float* __restrict__ Wm, const float* __restrict__ bias,
        float* __restrict__ outA, float* __restrict__ outL, int sideoff) {
    extern __shared__ float smf[];
    const uint32_t sbase = smem_u32(smf);
    const int tid = threadIdx.x;
    const int lane = tid & 31, wid = tid >> 5;
    const int warpM = wid >> 2, warpN = wid & 3;
    const int gid = lane >> 2, t4 = lane & 3;
    const int n0 = blockIdx.x * 128;

    const float* A;
    float* C;
    size_t m0;
    if (MODE == 0) {
        m0 = (size_t)blockIdx.z * S_ + blockIdx.y * 128;
        A = g_padded + ((size_t)blockIdx.z * SP_ + blockIdx.y * 128 + sideoff) * H_;
        C = side ? g_ro : g_lo;
    } else if (MODE == 1) {
        m0 = (size_t)blockIdx.y * 128;
        A = g_ln + m0 * H_;
        C = g_h;
    } else {
        m0 = (size_t)blockIdx.y * 128;
        A = g_h + m0 * H_;
        C = side ? g_ro : g_lo;
    }

    // per-thread cp.async assignments (4 A chunks + 4 B chunks of 16B each)
    const int ar0 = tid >> 3, akc = tid & 7;     // A: rows step 32
    const int br0 = tid >> 5, bnc = tid & 31;    // B: rows step 8

    float c[4][4][4];
#pragma unroll
    for (int i = 0; i < 4; i++)
#pragma unroll
        for (int j = 0; j < 4; j++)
#pragma unroll
            for (int q = 0; q < 4; q++) c[i][j][q] = 0.f;

    auto loadStage = [&](int kt, int s) {
        const int k0 = kt * 32;
        uint32_t asb = sbase + (uint32_t)(s * STAGE_F) * 4;
        uint32_t bsb = asb + A_STAGE_F * 4;
#pragma unroll
        for (int i = 0; i < 4; i++) {
            int ar = ar0 + i * 32;
            cp_async16(asb + (ar * AS_STRIDE + akc * 4) * 4,
                       A + (size_t)ar * H_ + k0 + akc * 4);
            int br = br0 + i * 8;
            cp_async16(bsb + (br * BS_STRIDE + bnc * 4) * 4,
                       Wm + (size_t)(k0 + br) * H_ + n0 + bnc * 4);
        }
        CP_COMMIT();
    };

    loadStage(0, 0);
    if (KT > 1) loadStage(1, 1);

    for (int kt = 0; kt < KT; kt++) {
        if (kt + 1 < KT) cp_wait<1>();
        else cp_wait<0>();
        __syncthreads();
        if (kt + 2 < KT) loadStage(kt + 2, (kt + 2) % 3);

        const float* as = smf + (kt % 3) * STAGE_F;
        const float* bs = as + A_STAGE_F;
#pragma unroll
        for (int ks = 0; ks < 4; ks++) {
            uint32_t a[4][4], b[4][2];
#pragma unroll
            for (int mr = 0; mr < 4; mr++) {
                const float* p = as + (warpM * 64 + mr * 16 + gid) * AS_STRIDE + ks * 8;
                a[mr][0] = f2tf32(p[t4]);
                a[mr][1] = f2tf32(p[8 * AS_STRIDE + t4]);
                a[mr][2] = f2tf32(p[t4 + 4]);
                a[mr][3] = f2tf32(p[8 * AS_STRIDE + t4 + 4]);
            }
#pragma unroll
            for (int nr = 0; nr < 4; nr++) {
                int cl = warpN * 32 + nr * 8 + gid;
                b[nr][0] = f2tf32(bs[(ks * 8 + t4) * BS_STRIDE + cl]);
                b[nr][1] = f2tf32(bs[(ks * 8 + t4 + 4) * BS_STRIDE + cl]);
            }
#pragma unroll
            for (int mr = 0; mr < 4; mr++)
#pragma unroll
                for (int nr = 0; nr < 4; nr++) mma_tf32(c[mr][nr], a[mr], b[nr]);
        }
        __syncthreads();
    }

    // epilogue
#pragma unroll
    for (int mr = 0; mr < 4; mr++) {
        size_t r0 = m0 + warpM * 64 + mr * 16 + gid;
#pragma unroll
        for (int nr = 0; nr < 4; nr++) {
            int col = n0 + warpN * 32 + nr * 8 + t4 * 2;
            float2 bv = *(const float2*)(bias + col);
#pragma unroll
            for (int hh = 0; hh < 2; hh++) {
                size_t r = r0 + hh * 8;
                float v0 = c[mr][nr][hh * 2 + 0] + bv.x;
                float v1 = c[mr][nr][hh * 2 + 1] + bv.y;
                float* crow = C + r * H_ + col;
                if (MODE != 2) {
                    v0 = fmaxf(v0, 0.f);
                    v1 = fmaxf(v1, 0.f);
                    *(float2*)crow = make_float2(v0, v1);
                } else {
                    float2 rv = *(const float2*)crow;  // residual (in place)
                    v0 += rv.x;
                    v1 += rv.y;
                    float2 v = make_float2(v0, v1);
                    *(float2*)crow = v;
                    size_t bi = r >> 11, si = r & 2047;
                    *(float2*)(outA + (si * B_ + bi) * (size_t)(2 * H_) + col) = v;
                    if (outL)
                        *(float2*)(outL + (bi * S_ + si) * (size_t)(2 * H_) + col) = v;
                }
            }
        }
    }
}

// ---------------------------------------------------------------------------
extern "C" void kernel_launch(void* const* d_in, const int* in_sizes, int n_in,
                              void* d_out, int out_size) {
    const float* inputs = (const float*)d_in[0];
    const float* lp     = (const float*)d_in[1];
    const float* rp     = (const float*)d_in[2];
    const float* Wl     = (const float*)d_in[3];
    const float* bl     = (const float*)d_in[4];
    const float* Wr     = (const float*)d_in[5];
    const float* br     = (const float*)d_in[6];
    const float* lw1    = (const float*)d_in[7];
    const float* lb1    = (const float*)d_in[8];
    const float* lw2    = (const float*)d_in[9];
    const float* lb2    = (const float*)d_in[10];
    const float* lg     = (const float*)d_in[11];
    const float* lbeta  = (const float*)d_in[12];
    const float* rw1    = (const float*)d_in[13];
    const float* rb1    = (const float*)d_in[14];
    const float* rw2    = (const float*)d_in[15];
    const float* rb2    = (const float*)d_in[16];
    const float* rg     = (const float*)d_in[17];
    const float* rbeta  = (const float*)d_in[18];
    float* out = (float*)d_out;
    (void)in_sizes; (void)n_in; (void)out_size;

    cudaFuncSetAttribute(tc_gemm<0, 64>, cudaFuncAttributeMaxDynamicSharedMemorySize, SMEM_BYTES);
    cudaFuncSetAttribute(tc_gemm<1, 16>, cudaFuncAttributeMaxDynamicSharedMemorySize, SMEM_BYTES);
    cudaFuncSetAttribute(tc_gemm<2, 16>, cudaFuncAttributeMaxDynamicSharedMemorySize, SMEM_BYTES);

    // 1) pad
    int padTotal = B_ * SP_ * (H_ / 4);
    pad_kernel<<<(padTotal + 255) / 256, 256>>>(inputs, lp, rp);

    // 2) wide projections: lo = relu(left @ Wl + bl), ro = relu(right @ Wr + br)
    dim3 gwide(4, 16, 16);
    tc_gemm<0, 64><<<gwide, 256, SMEM_BYTES>>>(0, Wl, bl, nullptr, nullptr, 0);
    tc_gemm<0, 64><<<gwide, 256, SMEM_BYTES>>>(1, Wr, br, nullptr, nullptr, W_ + 1);

    // 3) residual FF layers
    dim3 glayer(4, 256, 1);
    for (int i = 0; i < L_; i++)
        for (int side = 0; side < 2; side++) {
            const float* w1 = (side ? rw1 : lw1) + (size_t)i * H_ * H_;
            const float* b1 = (side ? rb1 : lb1) + (size_t)i * H_;
            const float* w2 = (side ? rw2 : lw2) + (size_t)i * H_ * H_;
            const float* b2 = (side ? rb2 : lb2) + (size_t)i * H_;
            const float* gg = (side ? rg : lg) + (size_t)i * H_;
            const float* bt = (side ? rbeta : lbeta) + (size_t)i * H_;

            ln_kernel<<<BS_ / 8, 256>>>(side, gg, bt);
            tc_gemm<1, 16><<<glayer, 256, SMEM_BYTES>>>(side, w1, b1, nullptr, nullptr, 0);

            float* oall = out + (size_t)i * S_ * B_ * 2 * H_ + (size_t)side * H_;
            float* olast = (i == L_ - 1)
                ? out + (size_t)L_ * S_ * B_ * 2 * H_ + (size_t)side * H_
                : nullptr;
            tc_gemm<2, 16><<<glayer, 256, SMEM_BYTES>>>(side, w2, b2, oall, olast, 0);
        }
}

// round 4
// speedup vs baseline: 5.8167x; 1.8478x over previous
#include <cuda_runtime.h>
#include <cuda_fp16.h>
#include <cstdint>

#define B_ 16
#define S_ 2048
#define H_ 512
#define W_ 4
#define L_ 2
#define SP_ (S_ + 2 * W_)   // 2056
#define BS_ (B_ * S_)       // 32768

// ---------------------------------------------------------------------------
// Scratch (__device__ globals; allocation-free rule)
// ---------------------------------------------------------------------------
__device__ __align__(256) __half g_pad_h[B_ * SP_ * H_];   // fp16 padded input
__device__ __align__(256) float  g_lo[BS_ * H_];           // fp32 residual stream L
__device__ __align__(256) float  g_ro[BS_ * H_];           // fp32 residual stream R
__device__ __align__(256) __half g_h_h[BS_ * H_];          // fp16 hidden (GEMM2 A)
__device__ __align__(256) __half g_ln_h[BS_ * H_];         // fp16 LN out (GEMM1 A)
// fp16 weights: [Wl 2048x512][Wr 2048x512][8 x 512x512]
#define WOFF_WL 0
#define WOFF_WR (2048 * 512)
#define WOFF_LAYERS (2 * 2048 * 512)
__device__ __align__(256) __half g_wh[WOFF_LAYERS + 8 * 512 * 512];

// ---------------------------------------------------------------------------
// PTX helpers
// ---------------------------------------------------------------------------
__device__ __forceinline__ uint32_t smem_u32(const void* p) {
    uint32_t a;
    asm("{ .reg .u64 t; cvta.to.shared.u64 t, %1; cvt.u32.u64 %0, t; }" : "=r"(a) : "l"(p));
    return a;
}
__device__ __forceinline__ void cp_async16(uint32_t dst, const void* src) {
    asm volatile("cp.async.cg.shared.global [%0], [%1], 16;" :: "r"(dst), "l"(src) : "memory");
}
template <int N>
__device__ __forceinline__ void cp_wait() {
    asm volatile("cp.async.wait_group %0;" :: "n"(N) : "memory");
}
#define CP_COMMIT() asm volatile("cp.async.commit_group;" ::: "memory")

__device__ __forceinline__ void ldm_x4(uint32_t r[4], uint32_t addr) {
    asm volatile("ldmatrix.sync.aligned.m8n8.x4.shared.b16 {%0,%1,%2,%3}, [%4];"
        : "=r"(r[0]), "=r"(r[1]), "=r"(r[2]), "=r"(r[3]) : "r"(addr));
}
__device__ __forceinline__ void ldm_x4_t(uint32_t r[4], uint32_t addr) {
    asm volatile("ldmatrix.sync.aligned.m8n8.x4.trans.shared.b16 {%0,%1,%2,%3}, [%4];"
        : "=r"(r[0]), "=r"(r[1]), "=r"(r[2]), "=r"(r[3]) : "r"(addr));
}
__device__ __forceinline__ void mma_f16(float c[4], const uint32_t a[4],
                                        uint32_t b0, uint32_t b1) {
    asm volatile(
        "mma.sync.aligned.m16n8k16.row.col.f32.f16.f16.f32 "
        "{%0,%1,%2,%3}, {%4,%5,%6,%7}, {%8,%9}, {%0,%1,%2,%3};"
        : "+f"(c[0]), "+f"(c[1]), "+f"(c[2]), "+f"(c[3])
        : "r"(a[0]), "r"(a[1]), "r"(a[2]), "r"(a[3]), "r"(b0), "r"(b1));
}

// ---------------------------------------------------------------------------
// fp32 -> fp16 weight convert (dst = g_wh + woff)
// ---------------------------------------------------------------------------
__global__ void f2h_kernel(const float* __restrict__ src, int woff, int n8) {
    int i = blockIdx.x * blockDim.x + threadIdx.x;
    if (i >= n8) return;
    float4 v0 = ((const float4*)src)[2 * i];
    float4 v1 = ((const float4*)src)[2 * i + 1];
    __half2 h[4];
    h[0] = __floats2half2_rn(v0.x, v0.y);
    h[1] = __floats2half2_rn(v0.z, v0.w);
    h[2] = __floats2half2_rn(v1.x, v1.y);
    h[3] = __floats2half2_rn(v1.z, v1.w);
    ((uint4*)(g_wh + woff))[i] = *(uint4*)h;
}

// ---------------------------------------------------------------------------
// pad: [left ; inputs ; right] -> g_pad_h (fp16)
// ---------------------------------------------------------------------------
__global__ void pad_kernel(const float* __restrict__ inp,
                           const float* __restrict__ lp,
                           const float* __restrict__ rp) {
    const int H4 = H_ / 4;
    int idx = blockIdx.x * blockDim.x + threadIdx.x;
    if (idx >= B_ * SP_ * H4) return;
    int h4 = idx % H4;
    int t = idx / H4;
    int p = t % SP_;
    int b = t / SP_;
    float4 v;
    if (p < W_) v = ((const float4*)lp)[p * H4 + h4];
    else if (p < W_ + S_) v = ((const float4*)inp)[((size_t)b * S_ + (p - W_)) * H4 + h4];
    else v = ((const float4*)rp)[(p - W_ - S_) * H4 + h4];
    __half2 h[2];
    h[0] = __floats2half2_rn(v.x, v.y);
    h[1] = __floats2half2_rn(v.z, v.w);
    ((uint2*)g_pad_h)[idx] = *(uint2*)h;
}

// ---------------------------------------------------------------------------
// LayerNorm, one warp per row: g_ln_h = fp16(gamma*(X-mean)*rstd + beta)
// ---------------------------------------------------------------------------
__global__ void ln_kernel(int side, const float* __restrict__ gam,
                          const float* __restrict__ bet) {
    const float* X = side ? g_ro : g_lo;
    int gw = (blockIdx.x * blockDim.x + threadIdx.x) >> 5;
    int l = threadIdx.x & 31;
    const float4* x = (const float4*)(X + (size_t)gw * H_);
    float4 v[4];
    float s = 0.f, sq = 0.f;
#pragma unroll
    for (int j = 0; j < 4; j++) {
        v[j] = x[l + 32 * j];
        s += v[j].x + v[j].y + v[j].z + v[j].w;
        sq += v[j].x * v[j].x + v[j].y * v[j].y + v[j].z * v[j].z + v[j].w * v[j].w;
    }
#pragma unroll
    for (int o = 16; o; o >>= 1) {
        s += __shfl_xor_sync(0xffffffffu, s, o);
        sq += __shfl_xor_sync(0xffffffffu, sq, o);
    }
    float mean = s * (1.0f / H_);
    float var = sq * (1.0f / H_) - mean * mean;
    float rstd = rsqrtf(fmaxf(var, 0.f) + 1e-5f);
    uint2* y = (uint2*)(g_ln_h + (size_t)gw * H_);
    const float4* g4 = (const float4*)gam;
    const float4* b4 = (const float4*)bet;
#pragma unroll
    for (int j = 0; j < 4; j++) {
        float4 gv = g4[l + 32 * j], bv = b4[l + 32 * j];
        __half2 h[2];
        h[0] = __floats2half2_rn((v[j].x - mean) * rstd * gv.x + bv.x,
                                 (v[j].y - mean) * rstd * gv.y + bv.y);
        h[1] = __floats2half2_rn((v[j].z - mean) * rstd * gv.z + bv.z,
                                 (v[j].w - mean) * rstd * gv.w + bv.w);
        y[l + 32 * j] = *(uint2*)h;
    }
}

// ---------------------------------------------------------------------------
// fp16 mma.sync GEMM: 128x128 tile, BK=32, 3-stage cp.async pipeline.
// 256 threads = 8 warps (2 x 4), warp tile 64x32, mma m16n8k16, ldmatrix frags.
// MODE 0: A = g_pad_h windows,  C = relu(A@W + b) fp32 -> g_lo/g_ro
// MODE 1: A = g_ln_h,           C = relu(A@W + b) fp16 -> g_h_h
// MODE 2: A = g_h_h, y = X + A@W + b -> X (fp32, in place), out_all, out_last
// ---------------------------------------------------------------------------
constexpr int A_STAGE_B = 128 * 80;     // 10240 B (stride 80 B = 40 halves)
constexpr int B_STAGE_B = 32 * 272;     // 8704 B  (stride 272 B = 136 halves)
constexpr int STAGE_B = A_STAGE_B + B_STAGE_B;  // 18944 B
constexpr int SMEM_BYTES = 3 * STAGE_B;         // 56832 B

template <int MODE, int KT>  // KT = K / 32
__global__ void __launch_bounds__(256, 2)
tc_gemm(int side, int woff, const float* __restrict__ bias,
        float* __restrict__ outA, float* __restrict__ outL, int sideoff) {
    extern __shared__ char smraw[];
    const uint32_t sbase = smem_u32(smraw);
    const int tid = threadIdx.x;
    const int lane = tid & 31, wid = tid >> 5;
    const int warpM = wid >> 2, warpN = wid & 3;
    const int gid = lane >> 2, t4 = lane & 3;
    const int lane15 = lane & 15, laneHi = lane >> 4;
    const int n0 = blockIdx.x * 128;

    const __half* A;
    size_t m0;
    if (MODE == 0) {
        m0 = (size_t)blockIdx.z * S_ + blockIdx.y * 128;
        A = g_pad_h + ((size_t)blockIdx.z * SP_ + blockIdx.y * 128 + sideoff) * H_;
    } else if (MODE == 1) {
        m0 = (size_t)blockIdx.y * 128;
        A = g_ln_h + m0 * H_;
    } else {
        m0 = (size_t)blockIdx.y * 128;
        A = g_h_h + m0 * H_;
    }
    const __half* Wm = g_wh + woff;
    float* X = side ? g_ro : g_lo;

    float c[4][4][4];
#pragma unroll
    for (int i = 0; i < 4; i++)
#pragma unroll
        for (int j = 0; j < 4; j++)
#pragma unroll
            for (int q = 0; q < 4; q++) c[i][j][q] = 0.f;

    auto loadStage = [&](int kt, int s) {
        const int k0 = kt * 32;
        uint32_t base = sbase + (uint32_t)s * STAGE_B;
#pragma unroll
        for (int i = 0; i < 2; i++) {
            int ch = tid + i * 256;
            int ar = ch >> 2, ac = ch & 3;
            cp_async16(base + ar * 80 + ac * 16, A + (size_t)ar * H_ + k0 + ac * 8);
            int br = ch >> 4, bc = ch & 15;
            cp_async16(base + A_STAGE_B + br * 272 + bc * 16,
                       Wm + (size_t)(k0 + br) * H_ + n0 + bc * 8);
        }
        CP_COMMIT();
    };

    loadStage(0, 0);
    if (KT > 1) loadStage(1, 1);

    for (int kt = 0; kt < KT; kt++) {
        if (kt + 1 < KT) cp_wait<1>();
        else cp_wait<0>();
        __syncthreads();
        if (kt + 2 < KT) loadStage(kt + 2, (kt + 2) % 3);

        const uint32_t a_base = sbase + (uint32_t)((kt % 3) * STAGE_B);
        const uint32_t b_base = a_base + A_STAGE_B;
#pragma unroll
        for (int ks = 0; ks < 2; ks++) {
            uint32_t a[4][4], bb[2][4];
#pragma unroll
            for (int mr = 0; mr < 4; mr++)
                ldm_x4(a[mr], a_base + (warpM * 64 + mr * 16 + lane15) * 80
                                 + ks * 32 + laneHi * 16);
#pragma unroll
            for (int np = 0; np < 2; np++)
                ldm_x4_t(bb[np], b_base + (ks * 16 + lane15) * 272
                                   + (warpN * 32 + np * 16 + laneHi * 8) * 2);
#pragma unroll
            for (int mr = 0; mr < 4; mr++)
#pragma unroll
                for (int np = 0; np < 2; np++) {
                    mma_f16(c[mr][2 * np + 0], a[mr], bb[np][0], bb[np][1]);
                    mma_f16(c[mr][2 * np + 1], a[mr], bb[np][2], bb[np][3]);
                }
        }
        __syncthreads();
    }

    // epilogue: c[mr][nr] rows (gid, gid+8), cols t4*2, t4*2+1
#pragma unroll
    for (int mr = 0; mr < 4; mr++) {
        size_t r0 = m0 + warpM * 64 + mr * 16 + gid;
#pragma unroll
        for (int nr = 0; nr < 4; nr++) {
            int col = n0 + warpN * 32 + nr * 8 + t4 * 2;
            float2 bv = *(const float2*)(bias + col);
#pragma unroll
            for (int hh = 0; hh < 2; hh++) {
                size_t r = r0 + hh * 8;
                float v0 = c[mr][nr][hh * 2 + 0] + bv.x;
                float v1 = c[mr][nr][hh * 2 + 1] + bv.y;
                if (MODE == 0) {
                    *(float2*)(X + r * H_ + col) =
                        make_float2(fmaxf(v0, 0.f), fmaxf(v1, 0.f));
                } else if (MODE == 1) {
                    __half2 h = __floats2half2_rn(fmaxf(v0, 0.f), fmaxf(v1, 0.f));
                    *(__half2*)(g_h_h + r * H_ + col) = h;
                } else {
                    float* crow = X + r * H_ + col;
                    float2 rv = *(const float2*)crow;
                    float2 v = make_float2(v0 + rv.x, v1 + rv.y);
                    *(float2*)crow = v;
                    size_t bi = r >> 11, si = r & 2047;
                    *(float2*)(outA + (si * B_ + bi) * (size_t)(2 * H_) + col) = v;
                    if (outL)
                        *(float2*)(outL + (bi * S_ + si) * (size_t)(2 * H_) + col) = v;
                }
            }
        }
    }
}

// ---------------------------------------------------------------------------
extern "C" void kernel_launch(void* const* d_in, const int* in_sizes, int n_in,
                              void* d_out, int out_size) {
    const float* inputs = (const float*)d_in[0];
    const float* lp     = (const float*)d_in[1];
    const float* rp     = (const float*)d_in[2];
    const float* Wl     = (const float*)d_in[3];
    const float* bl     = (const float*)d_in[4];
    const float* Wr     = (const float*)d_in[5];
    const float* br     = (const float*)d_in[6];
    const float* lw1    = (const float*)d_in[7];
    const float* lb1    = (const float*)d_in[8];
    const float* lw2    = (const float*)d_in[9];
    const float* lb2    = (const float*)d_in[10];
    const float* lg     = (const float*)d_in[11];
    const float* lbeta  = (const float*)d_in[12];
    const float* rw1    = (const float*)d_in[13];
    const float* rb1    = (const float*)d_in[14];
    const float* rw2    = (const float*)d_in[15];
    const float* rb2    = (const float*)d_in[16];
    const float* rg     = (const float*)d_in[17];
    const float* rbeta  = (const float*)d_in[18];
    float* out = (float*)d_out;
    (void)in_sizes; (void)n_in; (void)out_size;

    cudaFuncSetAttribute(tc_gemm<0, 64>, cudaFuncAttributeMaxDynamicSharedMemorySize, SMEM_BYTES);
    cudaFuncSetAttribute(tc_gemm<1, 16>, cudaFuncAttributeMaxDynamicSharedMemorySize, SMEM_BYTES);
    cudaFuncSetAttribute(tc_gemm<2, 16>, cudaFuncAttributeMaxDynamicSharedMemorySize, SMEM_BYTES);

    // 1) pad (fp16) + weight conversions
    int padTotal = B_ * SP_ * (H_ / 4);
    pad_kernel<<<(padTotal + 255) / 256, 256>>>(inputs, lp, rp);

    const int WIDE8 = 2048 * 512 / 8, LAY8 = 512 * 512 / 8;
    f2h_kernel<<<(WIDE8 + 255) / 256, 256>>>(Wl, WOFF_WL, WIDE8);
    f2h_kernel<<<(WIDE8 + 255) / 256, 256>>>(Wr, WOFF_WR, WIDE8);
    const float* lw[2][2] = {{lw1, lw2}, {rw1, rw2}};
    for (int i = 0; i < L_; i++)
        for (int side = 0; side < 2; side++)
            for (int which = 0; which < 2; which++) {
                int woff = WOFF_LAYERS + (((i * 2 + side) * 2) + which) * (512 * 512);
                f2h_kernel<<<(LAY8 + 255) / 256, 256>>>(
                    lw[side][which] + (size_t)i * H_ * H_, woff, LAY8);
            }

    // 2) wide projections
    dim3 gwide(4, 16, 16);
    tc_gemm<0, 64><<<gwide, 256, SMEM_BYTES>>>(0, WOFF_WL, bl, nullptr, nullptr, 0);
    tc_gemm<0, 64><<<gwide, 256, SMEM_BYTES>>>(1, WOFF_WR, br, nullptr, nullptr, W_ + 1);

    // 3) residual FF layers
    dim3 glayer(4, 256, 1);
    for (int i = 0; i < L_; i++)
        for (int side = 0; side < 2; side++) {
            const float* b1 = (side ? rb1 : lb1) + (size_t)i * H_;
            const float* b2 = (side ? rb2 : lb2) + (size_t)i * H_;
            const float* gg = (side ? rg : lg) + (size_t)i * H_;
            const float* bt = (side ? rbeta : lbeta) + (size_t)i * H_;
            int w1off = WOFF_LAYERS + (((i * 2 + side) * 2) + 0) * (512 * 512);
            int w2off = WOFF_LAYERS + (((i * 2 + side) * 2) + 1) * (512 * 512);

            ln_kernel<<<BS_ / 8, 256>>>(side, gg, bt);
            tc_gemm<1, 16><<<glayer, 256, SMEM_BYTES>>>(side, w1off, b1, nullptr, nullptr, 0);

            float* oall = out + (size_t)i * S_ * B_ * 2 * H_ + (size_t)side * H_;
            float* olast = (i == L_ - 1)
                ? out + (size_t)L_ * S_ * B_ * 2 * H_ + (size_t)side * H_
                : nullptr;
            tc_gemm<2, 16><<<glayer, 256, SMEM_BYTES>>>(side, w2off, b2, oall, olast, 0);
        }
}

// round 6
// speedup vs baseline: 5.9432x; 1.0217x over previous
#include <cuda_runtime.h>
#include <cuda_fp16.h>
#include <cstdint>

#define B_ 16
#define S_ 2048
#define H_ 512
#define W_ 4
#define L_ 2
#define SP_ (S_ + 2 * W_)   // 2056
#define BS_ (B_ * S_)       // 32768

// ---------------------------------------------------------------------------
// Scratch (__device__ globals; allocation-free rule)
// ---------------------------------------------------------------------------
__device__ __align__(256) __half g_pad_h[B_ * SP_ * H_];     // fp16 padded input
__device__ __align__(256) float  g_lo[BS_ * H_];             // fp32 residual L
__device__ __align__(256) float  g_ro[BS_ * H_];             // fp32 residual R
__device__ __align__(256) __half g_u[2 * BS_ * H_];          // fp16 x*gamma (GEMM1 A), per side
__device__ __align__(256) __half g_h[2 * BS_ * H_];          // fp16 hidden (GEMM2 A), per side
__device__ __align__(256) float  g_stats[4 * BS_ * 2];       // (sum, sumsq) x 4 phases
__device__ __align__(256) float  g_q[4 * H_];                // gamma @ W1 per (layer,side)
__device__ __align__(256) float  g_p[4 * H_];                // beta @ W1 + b1
// fp16 weights, layout matches f2h_all linear order:
#define OFF_WL  0
#define OFF_WR  1048576
#define OFF_LW1 2097152
#define OFF_LW2 2621440
#define OFF_RW1 3145728
#define OFF_RW2 3670016
__device__ __align__(256) __half g_wh[4194304];

// ---------------------------------------------------------------------------
// PTX helpers
// ---------------------------------------------------------------------------
__device__ __forceinline__ uint32_t smem_u32(const void* p) {
    uint32_t a;
    asm("{ .reg .u64 t; cvta.to.shared.u64 t, %1; cvt.u32.u64 %0, t; }" : "=r"(a) : "l"(p));
    return a;
}
__device__ __forceinline__ void cp_async16(uint32_t dst, const void* src) {
    asm volatile("cp.async.cg.shared.global [%0], [%1], 16;" :: "r"(dst), "l"(src) : "memory");
}
template <int N>
__device__ __forceinline__ void cp_wait() {
    asm volatile("cp.async.wait_group %0;" :: "n"(N) : "memory");
}
#define CP_COMMIT() asm volatile("cp.async.commit_group;" ::: "memory")

__device__ __forceinline__ void ldm_x4(uint32_t r[4], uint32_t addr) {
    asm volatile("ldmatrix.sync.aligned.m8n8.x4.shared.b16 {%0,%1,%2,%3}, [%4];"
        : "=r"(r[0]), "=r"(r[1]), "=r"(r[2]), "=r"(r[3]) : "r"(addr));
}
__device__ __forceinline__ void ldm_x4_t(uint32_t r[4], uint32_t addr) {
    asm volatile("ldmatrix.sync.aligned.m8n8.x4.trans.shared.b16 {%0,%1,%2,%3}, [%4];"
        : "=r"(r[0]), "=r"(r[1]), "=r"(r[2]), "=r"(r[3]) : "r"(addr));
}
__device__ __forceinline__ void mma_f16(float c[4], const uint32_t a[4],
                                        uint32_t b0, uint32_t b1) {
    asm volatile(
        "mma.sync.aligned.m16n8k16.row.col.f32.f16.f16.f32 "
        "{%0,%1,%2,%3}, {%4,%5,%6,%7}, {%8,%9}, {%0,%1,%2,%3};"
        : "+f"(c[0]), "+f"(c[1]), "+f"(c[2]), "+f"(c[3])
        : "r"(a[0]), "r"(a[1]), "r"(a[2]), "r"(a[3]), "r"(b0), "r"(b1));
}

// ---------------------------------------------------------------------------
// Single kernel: convert ALL fp32 weights -> fp16 into g_wh (linear layout)
// ---------------------------------------------------------------------------
__global__ void f2h_all(const float* __restrict__ Wl, const float* __restrict__ Wr,
                        const float* __restrict__ lw1, const float* __restrict__ lw2,
                        const float* __restrict__ rw1, const float* __restrict__ rw2) {
    int i = blockIdx.x * blockDim.x + threadIdx.x;   // uint4 index (8 halves)
    if (i >= 524288) return;
    const float* src;
    int off;
    if (i < 131072)      { src = Wl;  off = i; }
    else if (i < 262144) { src = Wr;  off = i - 131072; }
    else if (i < 327680) { src = lw1; off = i - 262144; }
    else if (i < 393216) { src = lw2; off = i - 327680; }
    else if (i < 458752) { src = rw1; off = i - 393216; }
    else                 { src = rw2; off = i - 458752; }
    float4 v0 = ((const float4*)src)[2 * off];
    float4 v1 = ((const float4*)src)[2 * off + 1];
    __half2 h[4];
    h[0] = __floats2half2_rn(v0.x, v0.y);
    h[1] = __floats2half2_rn(v0.z, v0.w);
    h[2] = __floats2half2_rn(v1.x, v1.y);
    h[3] = __floats2half2_rn(v1.z, v1.w);
    ((uint4*)g_wh)[i] = *(uint4*)h;
}

// ---------------------------------------------------------------------------
// prep: q = gamma @ W1, p = beta @ W1 + b1, per combo = layer*2 + side
// ---------------------------------------------------------------------------
__global__ void prep_qp(const float* __restrict__ lw1, const float* __restrict__ rw1,
                        const float* __restrict__ lg, const float* __restrict__ lbeta,
                        const float* __restrict__ lb1,
                        const float* __restrict__ rg, const float* __restrict__ rbeta,
                        const float* __restrict__ rb1) {
    int combo = blockIdx.y;
    int layer = combo >> 1, side = combo & 1;
    const float* Wm = (side ? rw1 : lw1) + (size_t)layer * H_ * H_;
    const float* ga = (side ? rg : lg) + layer * H_;
    const float* be = (side ? rbeta : lbeta) + layer * H_;
    const float* b1 = (side ? rb1 : lb1) + layer * H_;
    int j = blockIdx.x * 128 + threadIdx.x;
    float q = 0.f, p = 0.f;
    for (int k = 0; k < H_; k++) {
        float w = Wm[(size_t)k * H_ + j];
        q += ga[k] * w;
        p += be[k] * w;
    }
    g_q[combo * H_ + j] = q;
    g_p[combo * H_ + j] = p + b1[j];
}

// ---------------------------------------------------------------------------
// pad: [left ; inputs ; right] -> g_pad_h (fp16)
// ---------------------------------------------------------------------------
__global__ void pad_kernel(const float* __restrict__ inp,
                           const float* __restrict__ lp,
                           const float* __restrict__ rp) {
    const int H4 = H_ / 4;
    int idx = blockIdx.x * blockDim.x + threadIdx.x;
    if (idx >= B_ * SP_ * H4) return;
    int h4 = idx % H4;
    int t = idx / H4;
    int p = t % SP_;
    int b = t / SP_;
    float4 v;
    if (p < W_) v = ((const float4*)lp)[p * H4 + h4];
    else if (p < W_ + S_) v = ((const float4*)inp)[((size_t)b * S_ + (p - W_)) * H4 + h4];
    else v = ((const float4*)rp)[(p - W_ - S_) * H4 + h4];
    __half2 h[2];
    h[0] = __floats2half2_rn(v.x, v.y);
    h[1] = __floats2half2_rn(v.z, v.w);
    ((uint2*)g_pad_h)[idx] = *(uint2*)h;
}

// ---------------------------------------------------------------------------
// fp16 mma.sync GEMM: 128x128 tile, BK=32, 3-stage cp.async, 8 warps (2x4).
// MODE 0 (grid 4,16,32): wide proj. z -> (side, batch). Epilogue: relu(acc+b)
//        -> X fp32, u = fp16(v*gamma0), atomic stats phase side.
// MODE 1 (grid 4,256,2): A = g_u[side]. Epilogue: LN-corrected
//        v = rstd*acc - rstd*mu*q + p, relu -> g_h[side] fp16.
// MODE 2 (grid 4,256,2): A = g_h[side]. v = X + acc + b2 -> out_all (+ out_last
//        if last) at column side*H_ + col. If not last: X = v,
//        u = fp16(v*gamma_next), stats phase 2+side.
// ---------------------------------------------------------------------------
constexpr int A_STAGE_B = 128 * 80;
constexpr int B_STAGE_B = 32 * 272;
constexpr int STAGE_B = A_STAGE_B + B_STAGE_B;  // 18944 B
constexpr int SMEM_BYTES = 3 * STAGE_B;         // 56832 B

template <int MODE, int KT>
__global__ void __launch_bounds__(256, 2)
tc_gemm(int woffL, int woffR,
        const float* __restrict__ bL, const float* __restrict__ bR,
        const float* __restrict__ gamL, const float* __restrict__ gamR,
        int qp_base, int statsPhase, int ln_phase,
        float* __restrict__ outA, float* __restrict__ outL) {
    extern __shared__ char smraw[];
    const uint32_t sbase = smem_u32(smraw);
    const int tid = threadIdx.x;
    const int lane = tid & 31, wid = tid >> 5;
    const int warpM = wid >> 2, warpN = wid & 3;
    const int gid = lane >> 2, t4 = lane & 3;
    const int lane15 = lane & 15, laneHi = lane >> 4;
    const int n0 = blockIdx.x * 128;

    int side;
    size_t m0;
    const __half* A;
    if (MODE == 0) {
        side = blockIdx.z >> 4;
        int bb = blockIdx.z & 15;
        m0 = (size_t)bb * S_ + blockIdx.y * 128;
        A = g_pad_h + ((size_t)bb * SP_ + blockIdx.y * 128 + side * (W_ + 1)) * H_;
    } else {
        side = blockIdx.z;
        m0 = (size_t)blockIdx.y * 128;
        A = (MODE == 1 ? g_u : g_h) + ((size_t)side * BS_ + m0) * H_;
    }
    const __half* Wm = g_wh + (side ? woffR : woffL);
    float* X = side ? g_ro : g_lo;
    const float* bias = side ? bR : bL;
    const float* gam = side ? gamR : gamL;

    float c[4][4][4];
#pragma unroll
    for (int i = 0; i < 4; i++)
#pragma unroll
        for (int j = 0; j < 4; j++)
#pragma unroll
            for (int q = 0; q < 4; q++) c[i][j][q] = 0.f;

    auto loadStage = [&](int kt, int s) {
        const int k0 = kt * 32;
        uint32_t base = sbase + (uint32_t)s * STAGE_B;
#pragma unroll
        for (int i = 0; i < 2; i++) {
            int ch = tid + i * 256;
            int ar = ch >> 2, ac = ch & 3;
            cp_async16(base + ar * 80 + ac * 16, A + (size_t)ar * H_ + k0 + ac * 8);
            int br = ch >> 4, bc = ch & 15;
            cp_async16(base + A_STAGE_B + br * 272 + bc * 16,
                       Wm + (size_t)(k0 + br) * H_ + n0 + bc * 8);
        }
        CP_COMMIT();
    };

    loadStage(0, 0);
    if (KT > 1) loadStage(1, 1);

    for (int kt = 0; kt < KT; kt++) {
        if (kt + 1 < KT) cp_wait<1>();
        else cp_wait<0>();
        __syncthreads();
        if (kt + 2 < KT) loadStage(kt + 2, (kt + 2) % 3);

        const uint32_t a_base = sbase + (uint32_t)((kt % 3) * STAGE_B);
        const uint32_t b_base = a_base + A_STAGE_B;
#pragma unroll
        for (int ks = 0; ks < 2; ks++) {
            uint32_t a[4][4], bb2[2][4];
#pragma unroll
            for (int mr = 0; mr < 4; mr++)
                ldm_x4(a[mr], a_base + (warpM * 64 + mr * 16 + lane15) * 80
                                 + ks * 32 + laneHi * 16);
#pragma unroll
            for (int np = 0; np < 2; np++)
                ldm_x4_t(bb2[np], b_base + (ks * 16 + lane15) * 272
                                    + (warpN * 32 + np * 16 + laneHi * 8) * 2);
#pragma unroll
            for (int mr = 0; mr < 4; mr++)
#pragma unroll
                for (int np = 0; np < 2; np++) {
                    mma_f16(c[mr][2 * np + 0], a[mr], bb2[np][0], bb2[np][1]);
                    mma_f16(c[mr][2 * np + 1], a[mr], bb2[np][2], bb2[np][3]);
                }
        }
        __syncthreads();
    }

    // ---------------- epilogue ----------------
    const int colbase = n0 + warpN * 32 + t4 * 2;
    __half* uSide = g_u + (size_t)side * BS_ * H_;

    if (MODE == 1) {
        const int cb = (qp_base + side) * H_;
        const float* stats = g_stats + (size_t)(ln_phase + side) * BS_ * 2;
        __half* hSide = g_h + (size_t)side * BS_ * H_;
#pragma unroll
        for (int mr = 0; mr < 4; mr++) {
#pragma unroll
            for (int hh = 0; hh < 2; hh++) {
                size_t r = m0 + warpM * 64 + mr * 16 + gid + hh * 8;
                float2 st = *(const float2*)(stats + r * 2);
                float mu = st.x * (1.0f / H_);
                float var = st.y * (1.0f / H_) - mu * mu;
                float rstd = rsqrtf(fmaxf(var, 0.f) + 1e-5f);
                float mt = -rstd * mu;
                __half* hrow = hSide + r * H_;
#pragma unroll
                for (int nr = 0; nr < 4; nr++) {
                    int col = colbase + nr * 8;
                    float2 q2 = *(const float2*)(g_q + cb + col);
                    float2 p2 = *(const float2*)(g_p + cb + col);
                    float v0 = fmaf(rstd, c[mr][nr][hh * 2 + 0], fmaf(mt, q2.x, p2.x));
                    float v1 = fmaf(rstd, c[mr][nr][hh * 2 + 1], fmaf(mt, q2.y, p2.y));
                    *(__half2*)(hrow + col) =
                        __floats2half2_rn(fmaxf(v0, 0.f), fmaxf(v1, 0.f));
                }
            }
        }
        return;
    }

    // MODE 0 / MODE 2
    float2 bv[4], gv[4];
#pragma unroll
    for (int nr = 0; nr < 4; nr++) {
        bv[nr] = *(const float2*)(bias + colbase + nr * 8);
        if (MODE == 0 || statsPhase >= 0)
            gv[nr] = *(const float2*)(gam + colbase + nr * 8);
    }
    float* statsDst = (statsPhase >= 0)
        ? g_stats + (size_t)(statsPhase + side) * BS_ * 2 : (float*)0;
    const int outcol0 = colbase + side * H_;   // concat offset in [.,.,2H] outputs

#pragma unroll
    for (int mr = 0; mr < 4; mr++) {
#pragma unroll
        for (int hh = 0; hh < 2; hh++) {
            size_t r = m0 + warpM * 64 + mr * 16 + gid + hh * 8;
            float* xrow = X + r * H_;
            float s = 0.f, sq = 0.f;
#pragma unroll
            for (int nr = 0; nr < 4; nr++) {
                int col = colbase + nr * 8;
                float v0 = c[mr][nr][hh * 2 + 0] + bv[nr].x;
                float v1 = c[mr][nr][hh * 2 + 1] + bv[nr].y;
                if (MODE == 0) {
                    v0 = fmaxf(v0, 0.f);
                    v1 = fmaxf(v1, 0.f);
                    *(float2*)(xrow + col) = make_float2(v0, v1);
                } else {
                    float2 rv = *(const float2*)(xrow + col);
                    v0 += rv.x;
                    v1 += rv.y;
                    size_t bi = r >> 11, si = r & 2047;
                    int ocol = outcol0 + nr * 8;
                    *(float2*)(outA + (si * B_ + bi) * (size_t)(2 * H_) + ocol) =
                        make_float2(v0, v1);
                    if (outL)
                        *(float2*)(outL + (bi * S_ + si) * (size_t)(2 * H_) + ocol) =
                            make_float2(v0, v1);
                    if (statsPhase >= 0) *(float2*)(xrow + col) = make_float2(v0, v1);
                }
                if (MODE == 0 || statsPhase >= 0) {
                    *(__half2*)(uSide + r * H_ + col) =
                        __floats2half2_rn(v0 * gv[nr].x, v1 * gv[nr].y);
                    s += v0 + v1;
                    sq += v0 * v0 + v1 * v1;
                }
            }
            if (statsDst) {
                s += __shfl_xor_sync(0xffffffffu, s, 1);
                sq += __shfl_xor_sync(0xffffffffu, sq, 1);
                s += __shfl_xor_sync(0xffffffffu, s, 2);
                sq += __shfl_xor_sync(0xffffffffu, sq, 2);
                if (t4 == 0) {
                    atomicAdd(statsDst + r * 2, s);
                    atomicAdd(statsDst + r * 2 + 1, sq);
                }
            }
        }
    }
}

// ---------------------------------------------------------------------------
extern "C" void kernel_launch(void* const* d_in, const int* in_sizes, int n_in,
                              void* d_out, int out_size) {
    const float* inputs = (const float*)d_in[0];
    const float* lp     = (const float*)d_in[1];
    const float* rp     = (const float*)d_in[2];
    const float* Wl     = (const float*)d_in[3];
    const float* bl     = (const float*)d_in[4];
    const float* Wr     = (const float*)d_in[5];
    const float* br     = (const float*)d_in[6];
    const float* lw1    = (const float*)d_in[7];
    const float* lb1    = (const float*)d_in[8];
    const float* lw2    = (const float*)d_in[9];
    const float* lb2    = (const float*)d_in[10];
    const float* lg     = (const float*)d_in[11];
    const float* lbeta  = (const float*)d_in[12];
    const float* rw1    = (const float*)d_in[13];
    const float* rb1    = (const float*)d_in[14];
    const float* rw2    = (const float*)d_in[15];
    const float* rb2    = (const float*)d_in[16];
    const float* rg     = (const float*)d_in[17];
    const float* rbeta  = (const float*)d_in[18];
    float* out = (float*)d_out;
    (void)in_sizes; (void)n_in; (void)out_size;

    cudaFuncSetAttribute(tc_gemm<0, 64>, cudaFuncAttributeMaxDynamicSharedMemorySize, SMEM_BYTES);
    cudaFuncSetAttribute(tc_gemm<1, 16>, cudaFuncAttributeMaxDynamicSharedMemorySize, SMEM_BYTES);
    cudaFuncSetAttribute(tc_gemm<2, 16>, cudaFuncAttributeMaxDynamicSharedMemorySize, SMEM_BYTES);

    // 0) zero stats
    float* statsPtr;
    cudaGetSymbolAddress((void**)&statsPtr, g_stats);
    cudaMemsetAsync(statsPtr, 0, 4 * BS_ * 2 * sizeof(float));

    // 1) pad + weight convert + LN-fold precompute
    int padTotal = B_ * SP_ * (H_ / 4);
    pad_kernel<<<(padTotal + 255) / 256, 256>>>(inputs, lp, rp);
    f2h_all<<<2048, 256>>>(Wl, Wr, lw1, lw2, rw1, rw2);
    prep_qp<<<dim3(4, 4), 128>>>(lw1, rw1, lg, lbeta, lb1, rg, rbeta, rb1);

    // 2) wide projections, L+R merged (stats phase 0/1, u with layer-0 gamma)
    tc_gemm<0, 64><<<dim3(4, 16, 32), 256, SMEM_BYTES>>>(
        OFF_WL, OFF_WR, bl, br, lg, rg, 0, 0, 0, nullptr, nullptr);

    // 3) residual FF layers, L+R merged per launch
    for (int i = 0; i < L_; i++) {
        bool last = (i == L_ - 1);
        tc_gemm<1, 16><<<dim3(4, 256, 2), 256, SMEM_BYTES>>>(
            OFF_LW1 + i * 262144, OFF_RW1 + i * 262144,
            nullptr, nullptr, nullptr, nullptr,
            i * 2, -1, (i == 0) ? 0 : 2, nullptr, nullptr);

        float* oall = out + (size_t)i * S_ * B_ * 2 * H_;
        float* olast = last ? out + (size_t)L_ * S_ * B_ * 2 * H_ : nullptr;
        tc_gemm<2, 16><<<dim3(4, 256, 2), 256, SMEM_BYTES>>>(
            OFF_LW2 + i * 262144, OFF_RW2 + i * 262144,
            lb2 + (size_t)i * H_, rb2 + (size_t)i * H_,
            last ? nullptr : lg + (size_t)(i + 1) * H_,
            last ? nullptr : rg + (size_t)(i + 1) * H_,
            0, last ? -1 : 2, 0, oall, olast);
    }
}